// round 11
// baseline (speedup 1.0000x reference)
#include <cuda_runtime.h>
#include <cuda_fp16.h>
#include <cstdint>

#define BS   4
#define NN   2048
#define CIN  128
#define COUT 64
#define H    4
#define HD   256
#define TI   64
#define TJ   64
#define JH   1024
#define NJT  16
#define LOG2E 1.4426950408889634f

// device scratch (allocation-free)
__device__ __half g_hs_h[(size_t)BS * H * COUT * NN];  // [bh][d][n] fp16 (transposed)
__device__ float g_el[BS * H * NN];                    // pre-scaled by log2e
__device__ float g_er[BS * H * NN];                    // pre-scaled by log2e
__device__ float g_emax[BS * H];
__device__ float g_opart[2][(size_t)BS * NN * HD];
__device__ float g_lpart[2][BS * H * NN];

// K2 smem layout (3-slot ring)
#define PSTR 72
#define PBUF_BYTES  9216                 // 64*72*2
#define HSBUF_BYTES 10368                // 72*72*2 (rows 64..71 = ones block)
#define OFF_HS_BYTES 27648               // after 3 P slots
#define OFF_ER_F 14688                   // float idx; slot s at +s*192 {er,B,D}
#define OFF_EL_F 15264                   // head h at +h*192 {el,A,C}
#define OFF_EM_F 16032                   // emax[4]
#define SMEM_K2 64160

__device__ __forceinline__ uint32_t smem_u32(const void* p) {
    uint32_t a;
    asm("{ .reg .u64 t; cvta.to.shared.u64 t, %1; cvt.u32.u64 %0, t; }" : "=r"(a) : "l"(p));
    return a;
}
__device__ __forceinline__ float ex2f(float x) {
    float r;
    asm("ex2.approx.f32 %0, %1;" : "=f"(r) : "f"(x));
    return r;
}
__device__ __forceinline__ void mma_f16(float* d, const uint32_t* a, const uint32_t* b) {
    asm volatile(
        "mma.sync.aligned.m16n8k16.row.col.f32.f16.f16.f32 "
        "{%0,%1,%2,%3}, {%4,%5,%6,%7}, {%8,%9}, {%0,%1,%2,%3};"
        : "+f"(d[0]), "+f"(d[1]), "+f"(d[2]), "+f"(d[3])
        : "r"(a[0]), "r"(a[1]), "r"(a[2]), "r"(a[3]), "r"(b[0]), "r"(b[1]));
}
__device__ __forceinline__ void ldsm_x4(uint32_t* r, uint32_t addr) {
    asm volatile("ldmatrix.sync.aligned.m8n8.x4.shared.b16 {%0,%1,%2,%3}, [%4];"
                 : "=r"(r[0]), "=r"(r[1]), "=r"(r[2]), "=r"(r[3]) : "r"(addr));
}
__device__ __forceinline__ void ldsm_x2(uint32_t* r, uint32_t addr) {
    asm volatile("ldmatrix.sync.aligned.m8n8.x2.shared.b16 {%0,%1}, [%2];"
                 : "=r"(r[0]), "=r"(r[1]) : "r"(addr));
}
__device__ __forceinline__ void cp16(uint32_t dst, const void* src) {
    asm volatile("cp.async.ca.shared.global [%0], [%1], 16;" :: "r"(dst), "l"(src));
}
#define CP_COMMIT asm volatile("cp.async.commit_group;" ::: "memory")
#define CP_WAIT0  asm volatile("cp.async.wait_group 0;" ::: "memory")
#define CP_WAIT1  asm volatile("cp.async.wait_group 1;" ::: "memory")
#define BARS(id, n) asm volatile("bar.sync %0, %1;" :: "r"(id), "r"(n) : "memory")
#define BARA(id, n) asm volatile("bar.arrive %0, %1;" :: "r"(id), "r"(n) : "memory")

// ---------------- K1: hs = xs @ W1 -> g_hs_h (transposed fp16), scaled el/er ----------------
__global__ __launch_bounds__(256) void k1_gemm(const float* __restrict__ xs,
                                               const float* __restrict__ W1,
                                               const float* __restrict__ a_l,
                                               const float* __restrict__ a_r) {
    const int bx = blockIdx.x, head = blockIdx.y, b = blockIdx.z;
    const int tid = threadIdx.x;
    const int ig = tid >> 4, cg = tid & 15;
    const int r0 = ig * 4, c0 = cg * 4;

    __shared__ float As[32][68];
    __shared__ float Bs[32][68];
    __shared__ float sred[16][64];

    float acc[4][4] = {};
    const float* xbase = xs + ((size_t)(b * NN + bx * 64)) * CIN;
    const float* wbase = W1 + head * COUT;

    for (int kc = 0; kc < CIN; kc += 32) {
        int lin = tid;
        #pragma unroll
        for (int t = 0; t < 2; t++, lin += 256) {
            int r = lin >> 3, k4 = lin & 7;
            float4 v = *(const float4*)(xbase + r * CIN + kc + k4 * 4);
            As[k4 * 4 + 0][r] = v.x; As[k4 * 4 + 1][r] = v.y;
            As[k4 * 4 + 2][r] = v.z; As[k4 * 4 + 3][r] = v.w;
        }
        lin = tid;
        #pragma unroll
        for (int t = 0; t < 2; t++, lin += 256) {
            int k = lin >> 4, c4 = lin & 15;
            float4 v = *(const float4*)(wbase + (size_t)(kc + k) * HD + c4 * 4);
            *(float4*)&Bs[k][c4 * 4] = v;
        }
        __syncthreads();
        #pragma unroll
        for (int k = 0; k < 32; k++) {
            float4 aq = *(const float4*)&As[k][r0];
            float4 bq = *(const float4*)&Bs[k][c0];
            float ar[4] = {aq.x, aq.y, aq.z, aq.w};
            float br[4] = {bq.x, bq.y, bq.z, bq.w};
            #pragma unroll
            for (int r = 0; r < 4; r++)
                #pragma unroll
                for (int c = 0; c < 4; c++) acc[r][c] += ar[r] * br[c];
        }
        __syncthreads();
    }

    const int bh = b * H + head;
    #pragma unroll
    for (int c = 0; c < 4; c++) {
        __half2 lo = __floats2half2_rn(acc[0][c], acc[1][c]);
        __half2 hi = __floats2half2_rn(acc[2][c], acc[3][c]);
        uint2 w = {*(uint32_t*)&lo, *(uint32_t*)&hi};
        *(uint2*)(g_hs_h + ((size_t)(bh * COUT + c0 + c)) * NN + bx * 64 + r0) = w;
    }
    float pl[4] = {}, pr[4] = {};
    #pragma unroll
    for (int r = 0; r < 4; r++)
        #pragma unroll
        for (int c = 0; c < 4; c++) {
            pl[r] += acc[r][c] * __ldg(a_l + c0 + c);
            pr[r] += acc[r][c] * __ldg(a_r + c0 + c);
        }
    #pragma unroll
    for (int r = 0; r < 4; r++) sred[cg][r0 + r] = pl[r];
    __syncthreads();
    if (tid < 64) {
        float s = 0.f;
        #pragma unroll
        for (int g = 0; g < 16; g++) s += sred[g][tid];
        g_el[(size_t)bh * NN + bx * 64 + tid] = s * LOG2E;
    }
    __syncthreads();
    #pragma unroll
    for (int r = 0; r < 4; r++) sred[cg][r0 + r] = pr[r];
    __syncthreads();
    if (tid < 64) {
        float s = 0.f;
        #pragma unroll
        for (int g = 0; g < 16; g++) s += sred[g][tid];
        g_er[(size_t)bh * NN + bx * 64 + tid] = s * LOG2E;
    }
}

// ---------------- K1b: emax (scaled domain) ----------------
__global__ void k1b_max() {
    const int bh = blockIdx.x;
    __shared__ float sm[256];
    float m = -1e30f;
    for (int i = threadIdx.x; i < NN; i += 256)
        m = fmaxf(m, g_er[(size_t)bh * NN + i]);
    sm[threadIdx.x] = m;
    __syncthreads();
    for (int s = 128; s > 0; s >>= 1) {
        if (threadIdx.x < s) sm[threadIdx.x] = fmaxf(sm[threadIdx.x], sm[threadIdx.x + s]);
        __syncthreads();
    }
    if (threadIdx.x == 0) g_emax[bh] = sm[0];
}

// ---------------- K2 builder iteration (3-slot ring, lookahead producer) ----------------
__device__ __forceinline__ void builder_iter(
    float* sm, __half* smh, uint32_t smb, const float* __restrict__ adjs,
    int b, int i0, int half_, int bt, int c4, int rb,
    int g, const float* rel, const float* rA, const float* rC,
    float4* cur, float4* nxt)
{
    const int sg = g % 3, sn = (g + 1) % 3;
    const int jt = g & 15;
    // prefetch adj tile for next jt into regs (tile index depends only on jt)
    {
        const int jn = half_ * JH + ((jt + 1) & 15) * TJ;
        const float* apn = adjs + ((size_t)(b * NN + i0 + rb)) * NN + jn + c4 * 4;
        #pragma unroll
        for (int v = 0; v < 8; v++) nxt[v] = *(const float4*)(apn + (size_t)(v * 8) * NN);
    }
    if (g >= 2 && g < 63) BARS(4 + sn, 256);      // slot sn free (consumers done g-2)
    else if (g == 1 || g == 63) BARS(7, 128);     // builder-only: order er smem writes->reads
    if (g < 63) {
        // stage er(g+1) and HS(g+1) into slot sn
        const int gn = g + 1;
        const int hn = gn >> 4;
        const int jbn = half_ * JH + (gn & 15) * TJ;
        const int bhn = b * H + hn;
        if (bt < 64) {
            float er = g_er[(size_t)bhn * NN + jbn + bt];
            float u = er - sm[OFF_EM_F + hn];
            sm[OFF_ER_F + sn * 192 + bt] = er;
            sm[OFF_ER_F + sn * 192 + 64 + bt] = ex2f(u);
            sm[OFF_ER_F + sn * 192 + 128 + bt] = ex2f(0.1f * u);
        }
        uint32_t hB = smb + OFF_HS_BYTES + sn * HSBUF_BYTES;
        const __half* hsrc = g_hs_h + (size_t)bhn * COUT * NN + jbn;
        #pragma unroll
        for (int v = 0; v < 4; v++) {
            int idx = bt + v * 128;
            int d = idx >> 3, j8 = idx & 7;
            cp16(hB + (uint32_t)(d * PSTR + j8 * 8) * 2, hsrc + (size_t)d * NN + j8 * 8);
        }
        CP_COMMIT;
    }
    // build P(g) into slot sg (factorized exp): p = adj * (s>0 ? A*B : C*D)
    {
        float4 er4 = *(const float4*)(sm + OFF_ER_F + sg * 192 + c4 * 4);
        float4 B4  = *(const float4*)(sm + OFF_ER_F + sg * 192 + 64 + c4 * 4);
        float4 D4  = *(const float4*)(sm + OFF_ER_F + sg * 192 + 128 + c4 * 4);
        const float* erv = (const float*)&er4;
        const float* Bv  = (const float*)&B4;
        const float* Dv  = (const float*)&D4;
        __half* sPb = smh + (sg * PBUF_BYTES) / 2;
        #pragma unroll
        for (int v = 0; v < 8; v++) {
            int r = rb + v * 8;
            const float* av = (const float*)&cur[v];
            float p[4];
            #pragma unroll
            for (int e = 0; e < 4; e++) {
                float s = rel[v] + erv[e];
                float f1 = (s > 0.f) ? rA[v] : rC[v];
                float f2 = (s > 0.f) ? Bv[e] : Dv[e];
                p[e] = av[e] * f1 * f2;
            }
            __half2 p01 = __floats2half2_rn(p[0], p[1]);
            __half2 p23 = __floats2half2_rn(p[2], p[3]);
            uint2 w = {*(uint32_t*)&p01, *(uint32_t*)&p23};
            *(uint2*)(sPb + r * PSTR + c4 * 4) = w;
        }
    }
    if (g == 63) { CP_WAIT0; } else { CP_WAIT1; }   // HS(g) complete; HS(g+1) in flight
    BARA(1 + sg, 256);
}

// ---------------- K2: warp-specialized fp16 mma flash loop ----------------
__global__ __launch_bounds__(256, 2) void k2_attn(const float* __restrict__ adjs) {
    extern __shared__ float sm[];
    __half* smh = (__half*)sm;
    const uint32_t smb = smem_u32(sm);
    const int tid = threadIdx.x, wid = tid >> 5, lane = tid & 31;
    const int i0 = blockIdx.x * TI, half_ = blockIdx.y, b = blockIdx.z;

    // init ones rows (64..71) of all 3 HS slots
    for (int idx = tid; idx < 3 * 8 * PSTR; idx += 256) {
        int s = idx / (8 * PSTR);
        int rem = idx % (8 * PSTR);
        int r8 = rem / PSTR, c = rem % PSTR;
        smh[(OFF_HS_BYTES + s * HSBUF_BYTES) / 2 + (64 + r8) * PSTR + c] =
            (r8 == 0 && c < 64) ? __float2half(1.f) : __float2half(0.f);
    }
    // emax cache
    if (tid < 4) sm[OFF_EM_F + tid] = g_emax[b * H + tid];
    // prologue: el / A / C per head
    if (tid < 256) {
        int h = tid >> 6, r = tid & 63;
        int bh = b * H + h;
        float e = g_el[(size_t)bh * NN + i0 + r];
        float E = g_emax[bh];
        float t = e + E;
        float m = fmaxf(t, 0.1f * t);
        sm[OFF_EL_F + h * 192 + r] = e;
        sm[OFF_EL_F + h * 192 + 64 + r] = ex2f(t - m);
        sm[OFF_EL_F + h * 192 + 128 + r] = ex2f(0.1f * t - m);
    }
    // prologue staging for g=0 into slot 0 (builder threads)
    if (tid >= 128) {
        int bt0 = tid - 128;
        if (bt0 < 64) {
            float er = g_er[(size_t)(b * H) * NN + half_ * JH + bt0];
            float u = er - g_emax[b * H];
            sm[OFF_ER_F + bt0] = er;
            sm[OFF_ER_F + 64 + bt0] = ex2f(u);
            sm[OFF_ER_F + 128 + bt0] = ex2f(0.1f * u);
        }
        uint32_t hB = smb + OFF_HS_BYTES;
        const __half* hsrc = g_hs_h + (size_t)(b * H) * COUT * NN + half_ * JH;
        #pragma unroll
        for (int v = 0; v < 4; v++) {
            int idx = bt0 + v * 128;
            int d = idx >> 3, j8 = idx & 7;
            cp16(hB + (uint32_t)(d * PSTR + j8 * 8) * 2, hsrc + (size_t)d * NN + j8 * 8);
        }
        CP_COMMIT;
    }
    __syncthreads();

    if (wid >= 4) {
        // ---------------- builders ----------------
        const int bt = tid & 127;
        const int c4 = bt & 15, rb = bt >> 4;
        float4 ajA[8], ajB[8];
        {
            const float* ap0 = adjs + ((size_t)(b * NN + i0 + rb)) * NN + half_ * JH + c4 * 4;
            #pragma unroll
            for (int v = 0; v < 8; v++) ajA[v] = *(const float4*)(ap0 + (size_t)(v * 8) * NN);
        }
        for (int h = 0; h < H; h++) {
            float rel[8], rA[8], rC[8];
            #pragma unroll
            for (int v = 0; v < 8; v++) {
                int r = rb + v * 8;
                rel[v] = sm[OFF_EL_F + h * 192 + r];
                rA[v]  = sm[OFF_EL_F + h * 192 + 64 + r];
                rC[v]  = sm[OFF_EL_F + h * 192 + 128 + r];
            }
            #pragma unroll 1
            for (int jp = 0; jp < 8; jp++) {
                builder_iter(sm, smh, smb, adjs, b, i0, half_, bt, c4, rb,
                             h * NJT + 2 * jp, rel, rA, rC, ajA, ajB);
                builder_iter(sm, smh, smb, adjs, b, i0, half_, bt, c4, rb,
                             h * NJT + 2 * jp + 1, rel, rA, rC, ajB, ajA);
            }
        }
    } else {
        // ---------------- consumers ----------------
        const int gid = lane >> 2, tg = lane & 3;
        const uint32_t aRow = (uint32_t)(wid * 16 + (lane & 7) + ((lane >> 3) & 1) * 8);
        const uint32_t aOff = (aRow * PSTR + (lane >> 4) * 8) * 2;
        const uint32_t bRowL = (uint32_t)((lane & 7) + (lane >> 4) * 8);
        const uint32_t bOff = (bRowL * PSTR + ((lane >> 3) & 1) * 8) * 2;
        const int ol = lane & 15;
        const uint32_t oOff = (uint32_t)(((64 + (ol & 7)) * PSTR + ((ol >> 3) & 1) * 8) * 2);
        for (int h = 0; h < H; h++) {
            const int bh = b * H + h;
            float acc[9][4];
            #pragma unroll
            for (int nc = 0; nc < 9; nc++)
                #pragma unroll
                for (int e = 0; e < 4; e++) acc[nc][e] = 0.f;
            for (int jt = 0; jt < NJT; jt++) {
                const int g = h * NJT + jt, slot = g % 3;
                BARS(1 + slot, 256);
                uint32_t pA = smb + slot * PBUF_BYTES + aOff;
                uint32_t hB = smb + OFF_HS_BYTES + slot * HSBUF_BYTES;
                #pragma unroll
                for (int ks = 0; ks < 4; ks++) {
                    uint32_t a[4];
                    ldsm_x4(a, pA); pA += 32;
                    #pragma unroll
                    for (int p2 = 0; p2 < 4; p2++) {
                        uint32_t bb[4];
                        ldsm_x4(bb, hB + bOff + (uint32_t)p2 * (16 * PSTR * 2) + ks * 32);
                        mma_f16(acc[2 * p2], a, bb);
                        mma_f16(acc[2 * p2 + 1], a, bb + 2);
                    }
                    uint32_t oo[2];
                    ldsm_x2(oo, hB + oOff + ks * 32);
                    mma_f16(acc[8], a, oo);
                }
                BARA(4 + slot, 256);
            }
            // epilogue: unnormalized O + l partials
            const int r0 = i0 + wid * 16 + gid;
            float* ob = g_opart[half_] + ((size_t)b * NN) * HD;
            #pragma unroll
            for (int nc = 0; nc < 8; nc++) {
                int col = h * 64 + nc * 8 + 2 * tg;
                float2 v0 = {acc[nc][0], acc[nc][1]};
                float2 v1 = {acc[nc][2], acc[nc][3]};
                *(float2*)(ob + (size_t)r0 * HD + col) = v0;
                *(float2*)(ob + (size_t)(r0 + 8) * HD + col) = v1;
            }
            if (tg == 0) {
                g_lpart[half_][(size_t)bh * NN + r0] = acc[8][0];
                g_lpart[half_][(size_t)bh * NN + r0 + 8] = acc[8][2];
            }
        }
    }
}

// ---------------- K3: combine halves + normalize ----------------
__global__ __launch_bounds__(256) void k3_combine(float* __restrict__ out) {
    int idx = blockIdx.x * 256 + threadIdx.x;
    size_t flat = (size_t)idx * 4;
    int b   = (int)(flat / ((size_t)NN * HD));
    int rem = (int)(flat % ((size_t)NN * HD));
    int i = rem / HD;
    int h = (rem % HD) >> 6;
    size_t li = (size_t)(b * H + h) * NN + i;
    float l = g_lpart[0][li] + g_lpart[1][li];
    float inv = (l > 0.f) ? (1.f / l) : 0.f;
    float4 o0 = *(const float4*)(g_opart[0] + flat);
    float4 o1 = *(const float4*)(g_opart[1] + flat);
    float4 w = {(o0.x + o1.x) * inv, (o0.y + o1.y) * inv,
                (o0.z + o1.z) * inv, (o0.w + o1.w) * inv};
    *(float4*)(out + flat) = w;
}

extern "C" void kernel_launch(void* const* d_in, const int* in_sizes, int n_in,
                              void* d_out, int out_size) {
    const float* xs   = (const float*)d_in[0];
    const float* adjs = (const float*)d_in[1];
    const float* W1   = (const float*)d_in[2];
    const float* a_l  = (const float*)d_in[3];
    const float* a_r  = (const float*)d_in[4];
    float* out = (float*)d_out;

    cudaFuncSetAttribute(k2_attn, cudaFuncAttributeMaxDynamicSharedMemorySize, SMEM_K2);

    k1_gemm<<<dim3(32, 4, 4), 256>>>(xs, W1, a_l, a_r);
    k1b_max<<<16, 256>>>();
    k2_attn<<<dim3(32, 2, 4), 256, SMEM_K2>>>(adjs);
    k3_combine<<<(BS * NN * HD / 4) / 256, 256>>>(out);
}

// round 12
// speedup vs baseline: 1.1993x; 1.1993x over previous
#include <cuda_runtime.h>
#include <cuda_fp16.h>
#include <cstdint>

#define BS   4
#define NN   2048
#define CIN  128
#define COUT 64
#define H    4
#define HD   256
#define TI   64
#define TJ   64
#define JH   1024
#define NJT  16
#define LOG2E 1.4426950408889634f

// device scratch (allocation-free)
__device__ __half g_hs_h[(size_t)BS * H * COUT * NN];  // [bh][d][n] fp16 (transposed)
__device__ float g_el[BS * H * NN];                    // pre-scaled by log2e
__device__ float g_er[BS * H * NN];                    // pre-scaled by log2e
__device__ unsigned int g_emax_key[BS * H];            // float-ordered key (0-init; idempotent)
__device__ float g_opart[2][(size_t)BS * NN * HD];
__device__ float g_lpart[2][BS * H * NN];

// K2 smem layout (R7)
#define PSTR 72
#define PBUF_BYTES  9216
#define HSBUF_BYTES 10368
#define OFF_HS_BYTES 18432
#define OFF_ER_F 9792          // per buf {er[64],B[64],D[64]} x2
#define OFF_EL_F 10176         // per head {el[64],A[64],C[64]} x4
#define SMEM_K2 44032

__device__ __forceinline__ uint32_t smem_u32(const void* p) {
    uint32_t a;
    asm("{ .reg .u64 t; cvta.to.shared.u64 t, %1; cvt.u32.u64 %0, t; }" : "=r"(a) : "l"(p));
    return a;
}
__device__ __forceinline__ float ex2f(float x) {
    float r;
    asm("ex2.approx.f32 %0, %1;" : "=f"(r) : "f"(x));
    return r;
}
__device__ __forceinline__ unsigned int fenc(float f) {
    unsigned int b = __float_as_uint(f);
    return (b & 0x80000000u) ? ~b : (b | 0x80000000u);
}
__device__ __forceinline__ float fdec(unsigned int k) {
    unsigned int b = (k & 0x80000000u) ? (k ^ 0x80000000u) : ~k;
    return __uint_as_float(b);
}
__device__ __forceinline__ void mma_f16(float* d, const uint32_t* a, const uint32_t* b) {
    asm volatile(
        "mma.sync.aligned.m16n8k16.row.col.f32.f16.f16.f32 "
        "{%0,%1,%2,%3}, {%4,%5,%6,%7}, {%8,%9}, {%0,%1,%2,%3};"
        : "+f"(d[0]), "+f"(d[1]), "+f"(d[2]), "+f"(d[3])
        : "r"(a[0]), "r"(a[1]), "r"(a[2]), "r"(a[3]), "r"(b[0]), "r"(b[1]));
}
__device__ __forceinline__ void ldsm_x4(uint32_t* r, uint32_t addr) {
    asm volatile("ldmatrix.sync.aligned.m8n8.x4.shared.b16 {%0,%1,%2,%3}, [%4];"
                 : "=r"(r[0]), "=r"(r[1]), "=r"(r[2]), "=r"(r[3]) : "r"(addr));
}
__device__ __forceinline__ void ldsm_x2(uint32_t* r, uint32_t addr) {
    asm volatile("ldmatrix.sync.aligned.m8n8.x2.shared.b16 {%0,%1}, [%2];"
                 : "=r"(r[0]), "=r"(r[1]) : "r"(addr));
}
__device__ __forceinline__ void cp16(uint32_t dst, const void* src) {
    asm volatile("cp.async.ca.shared.global [%0], [%1], 16;" :: "r"(dst), "l"(src));
}
#define CP_COMMIT asm volatile("cp.async.commit_group;" ::: "memory")
#define CP_WAIT0  asm volatile("cp.async.wait_group 0;" ::: "memory")
#define BARS(id, n) asm volatile("bar.sync %0, %1;" :: "r"(id), "r"(n) : "memory")
#define BARA(id, n) asm volatile("bar.arrive %0, %1;" :: "r"(id), "r"(n) : "memory")

// ---------------- K1: hs = xs @ W1 -> g_hs_h (transposed fp16), scaled el/er, fused emax ----------------
__global__ __launch_bounds__(256) void k1_gemm(const float* __restrict__ xs,
                                               const float* __restrict__ W1,
                                               const float* __restrict__ a_l,
                                               const float* __restrict__ a_r) {
    const int bx = blockIdx.x, head = blockIdx.y, b = blockIdx.z;
    const int tid = threadIdx.x;
    const int ig = tid >> 4, cg = tid & 15;
    const int r0 = ig * 4, c0 = cg * 4;

    __shared__ float As[32][68];
    __shared__ float Bs[32][68];
    __shared__ float sred[16][64];
    __shared__ float smax[2];

    float acc[4][4] = {};
    const float* xbase = xs + ((size_t)(b * NN + bx * 64)) * CIN;
    const float* wbase = W1 + head * COUT;

    for (int kc = 0; kc < CIN; kc += 32) {
        int lin = tid;
        #pragma unroll
        for (int t = 0; t < 2; t++, lin += 256) {
            int r = lin >> 3, k4 = lin & 7;
            float4 v = *(const float4*)(xbase + r * CIN + kc + k4 * 4);
            As[k4 * 4 + 0][r] = v.x; As[k4 * 4 + 1][r] = v.y;
            As[k4 * 4 + 2][r] = v.z; As[k4 * 4 + 3][r] = v.w;
        }
        lin = tid;
        #pragma unroll
        for (int t = 0; t < 2; t++, lin += 256) {
            int k = lin >> 4, c4 = lin & 15;
            float4 v = *(const float4*)(wbase + (size_t)(kc + k) * HD + c4 * 4);
            *(float4*)&Bs[k][c4 * 4] = v;
        }
        __syncthreads();
        #pragma unroll
        for (int k = 0; k < 32; k++) {
            float4 aq = *(const float4*)&As[k][r0];
            float4 bq = *(const float4*)&Bs[k][c0];
            float ar[4] = {aq.x, aq.y, aq.z, aq.w};
            float br[4] = {bq.x, bq.y, bq.z, bq.w};
            #pragma unroll
            for (int r = 0; r < 4; r++)
                #pragma unroll
                for (int c = 0; c < 4; c++) acc[r][c] += ar[r] * br[c];
        }
        __syncthreads();
    }

    const int bh = b * H + head;
    // transposed fp16 store: g_hs_h[bh][d][n]
    #pragma unroll
    for (int c = 0; c < 4; c++) {
        __half2 lo = __floats2half2_rn(acc[0][c], acc[1][c]);
        __half2 hi = __floats2half2_rn(acc[2][c], acc[3][c]);
        uint2 w = {*(uint32_t*)&lo, *(uint32_t*)&hi};
        *(uint2*)(g_hs_h + ((size_t)(bh * COUT + c0 + c)) * NN + bx * 64 + r0) = w;
    }
    float pl[4] = {}, pr[4] = {};
    #pragma unroll
    for (int r = 0; r < 4; r++)
        #pragma unroll
        for (int c = 0; c < 4; c++) {
            pl[r] += acc[r][c] * __ldg(a_l + c0 + c);
            pr[r] += acc[r][c] * __ldg(a_r + c0 + c);
        }
    #pragma unroll
    for (int r = 0; r < 4; r++) sred[cg][r0 + r] = pl[r];
    __syncthreads();
    if (tid < 64) {
        float s = 0.f;
        #pragma unroll
        for (int g = 0; g < 16; g++) s += sred[g][tid];
        g_el[(size_t)bh * NN + bx * 64 + tid] = s * LOG2E;
    }
    __syncthreads();
    #pragma unroll
    for (int r = 0; r < 4; r++) sred[cg][r0 + r] = pr[r];
    __syncthreads();
    if (tid < 64) {
        float s = 0.f;
        #pragma unroll
        for (int g = 0; g < 16; g++) s += sred[g][tid];
        float es = s * LOG2E;
        g_er[(size_t)bh * NN + bx * 64 + tid] = es;
        // fused emax: warp max over the 64 er values (warps 0-1)
        float m = es;
        #pragma unroll
        for (int o = 16; o > 0; o >>= 1)
            m = fmaxf(m, __shfl_xor_sync(0xffffffffu, m, o));
        if ((tid & 31) == 0) smax[tid >> 5] = m;
    }
    __syncthreads();
    if (tid == 0)
        atomicMax(&g_emax_key[bh], fenc(fmaxf(smax[0], smax[1])));
}

// ---------------- K2 builder iteration (R7 form) ----------------
__device__ __forceinline__ void builder_iter(
    float* sm, __half* smh, uint32_t smb, const float* __restrict__ adjs,
    int b, int i0, int half_, int bt, int c4, int rb,
    int h, int jt, float Eh,
    const float* rel, const float* rA, const float* rC,
    float4* cur, float4* nxt)
{
    const int g = h * NJT + jt, buf = g & 1;
    const int bh = b * H + h;
    const int jbase = half_ * JH + jt * TJ;
    // prefetch next adj tile into regs (adj is h-independent)
    {
        const int jn = half_ * JH + ((jt + 1) & 15) * TJ;
        const float* apn = adjs + ((size_t)(b * NN + i0 + rb)) * NN + jn + c4 * 4;
        #pragma unroll
        for (int v = 0; v < 8; v++) nxt[v] = *(const float4*)(apn + (size_t)(v * 8) * NN);
    }
    if (g >= 2) BARS(3 + buf, 256);
    // stage er / B / D factors
    if (bt < 64) {
        float er = g_er[(size_t)bh * NN + jbase + bt];
        float u = er - Eh;
        sm[OFF_ER_F + buf * 192 + bt] = er;
        sm[OFF_ER_F + buf * 192 + 64 + bt] = ex2f(u);
        sm[OFF_ER_F + buf * 192 + 128 + bt] = ex2f(0.1f * u);
    }
    // cp.async HS fp16 tile [64 d][64 j]
    {
        uint32_t hB = smb + OFF_HS_BYTES + buf * HSBUF_BYTES;
        const __half* hsrc = g_hs_h + (size_t)bh * COUT * NN + jbase;
        #pragma unroll
        for (int v = 0; v < 4; v++) {
            int idx = bt + v * 128;
            int d = idx >> 3, j8 = idx & 7;
            cp16(hB + (uint32_t)(d * PSTR + j8 * 8) * 2, hsrc + (size_t)d * NN + j8 * 8);
        }
        CP_COMMIT;
    }
    BARS(5, 128);
    // build P (factorized exp): p = adj * (s>0 ? A*B : C*D)
    {
        float4 er4 = *(const float4*)(sm + OFF_ER_F + buf * 192 + c4 * 4);
        float4 B4  = *(const float4*)(sm + OFF_ER_F + buf * 192 + 64 + c4 * 4);
        float4 D4  = *(const float4*)(sm + OFF_ER_F + buf * 192 + 128 + c4 * 4);
        const float* erv = (const float*)&er4;
        const float* Bv  = (const float*)&B4;
        const float* Dv  = (const float*)&D4;
        __half* sPb = smh + (buf * PBUF_BYTES) / 2;
        #pragma unroll
        for (int v = 0; v < 8; v++) {
            int r = rb + v * 8;
            const float* av = (const float*)&cur[v];
            float p[4];
            #pragma unroll
            for (int e = 0; e < 4; e++) {
                float s = rel[v] + erv[e];
                float f1 = (s > 0.f) ? rA[v] : rC[v];
                float f2 = (s > 0.f) ? Bv[e] : Dv[e];
                p[e] = av[e] * f1 * f2;
            }
            __half2 p01 = __floats2half2_rn(p[0], p[1]);
            __half2 p23 = __floats2half2_rn(p[2], p[3]);
            uint2 w = {*(uint32_t*)&p01, *(uint32_t*)&p23};
            *(uint2*)(sPb + r * PSTR + c4 * 4) = w;
        }
    }
    CP_WAIT0;
    BARA(1 + buf, 256);
}

// ---------------- K2: warp-specialized fp16 mma flash loop (R7) ----------------
__global__ __launch_bounds__(256, 2) void k2_attn(const float* __restrict__ adjs) {
    extern __shared__ float sm[];
    __half* smh = (__half*)sm;
    const uint32_t smb = smem_u32(sm);
    const int tid = threadIdx.x, wid = tid >> 5, lane = tid & 31;
    const int i0 = blockIdx.x * TI, half_ = blockIdx.y, b = blockIdx.z;

    // init ones rows (64..71) of both HS buffers
    for (int idx = tid; idx < 2 * 8 * PSTR; idx += 256) {
        int buf = idx / (8 * PSTR);
        int rem = idx % (8 * PSTR);
        int r8 = rem / PSTR, c = rem % PSTR;
        smh[(OFF_HS_BYTES + buf * HSBUF_BYTES) / 2 + (64 + r8) * PSTR + c] =
            (r8 == 0 && c < 64) ? __float2half(1.f) : __float2half(0.f);
    }
    // prologue: el / A / C per head
    if (tid < 256) {
        int h = tid >> 6, r = tid & 63;
        int bh = b * H + h;
        float e = g_el[(size_t)bh * NN + i0 + r];
        float E = fdec(g_emax_key[bh]);
        float t = e + E;
        float m = fmaxf(t, 0.1f * t);
        sm[OFF_EL_F + h * 192 + r] = e;
        sm[OFF_EL_F + h * 192 + 64 + r] = ex2f(t - m);
        sm[OFF_EL_F + h * 192 + 128 + r] = ex2f(0.1f * t - m);
    }
    __syncthreads();

    if (wid >= 4) {
        // ---------------- builders ----------------
        const int bt = tid & 127;
        const int c4 = bt & 15, rb = bt >> 4;
        float4 ajA[8], ajB[8];
        {
            const float* ap0 = adjs + ((size_t)(b * NN + i0 + rb)) * NN + half_ * JH + c4 * 4;
            #pragma unroll
            for (int v = 0; v < 8; v++) ajA[v] = *(const float4*)(ap0 + (size_t)(v * 8) * NN);
        }
        for (int h = 0; h < H; h++) {
            const float Eh = fdec(g_emax_key[b * H + h]);
            float rel[8], rA[8], rC[8];
            #pragma unroll
            for (int v = 0; v < 8; v++) {
                int r = rb + v * 8;
                rel[v] = sm[OFF_EL_F + h * 192 + r];
                rA[v]  = sm[OFF_EL_F + h * 192 + 64 + r];
                rC[v]  = sm[OFF_EL_F + h * 192 + 128 + r];
            }
            #pragma unroll 1
            for (int jp = 0; jp < 8; jp++) {
                builder_iter(sm, smh, smb, adjs, b, i0, half_, bt, c4, rb,
                             h, 2 * jp, Eh, rel, rA, rC, ajA, ajB);
                builder_iter(sm, smh, smb, adjs, b, i0, half_, bt, c4, rb,
                             h, 2 * jp + 1, Eh, rel, rA, rC, ajB, ajA);
            }
        }
    } else {
        // ---------------- consumers ----------------
        const int gid = lane >> 2, tg = lane & 3;
        const uint32_t aRow = (uint32_t)(wid * 16 + (lane & 7) + ((lane >> 3) & 1) * 8);
        const uint32_t aOff = (aRow * PSTR + (lane >> 4) * 8) * 2;
        const uint32_t bRowL = (uint32_t)((lane & 7) + (lane >> 4) * 8);
        const uint32_t bOff = (bRowL * PSTR + ((lane >> 3) & 1) * 8) * 2;
        const int ol = lane & 15;
        const uint32_t oOff = (uint32_t)(((64 + (ol & 7)) * PSTR + ((ol >> 3) & 1) * 8) * 2);
        for (int h = 0; h < H; h++) {
            const int bh = b * H + h;
            float acc[9][4];
            #pragma unroll
            for (int nc = 0; nc < 9; nc++)
                #pragma unroll
                for (int e = 0; e < 4; e++) acc[nc][e] = 0.f;
            for (int jt = 0; jt < NJT; jt++) {
                const int g = h * NJT + jt, buf = g & 1;
                BARS(1 + buf, 256);
                uint32_t pA = smb + buf * PBUF_BYTES + aOff;
                uint32_t hB = smb + OFF_HS_BYTES + buf * HSBUF_BYTES;
                #pragma unroll
                for (int ks = 0; ks < 4; ks++) {
                    uint32_t a[4];
                    ldsm_x4(a, pA); pA += 32;
                    #pragma unroll
                    for (int p2 = 0; p2 < 4; p2++) {
                        uint32_t bb[4];
                        ldsm_x4(bb, hB + bOff + (uint32_t)p2 * (16 * PSTR * 2) + ks * 32);
                        mma_f16(acc[2 * p2], a, bb);
                        mma_f16(acc[2 * p2 + 1], a, bb + 2);
                    }
                    uint32_t oo[2];
                    ldsm_x2(oo, hB + oOff + ks * 32);
                    mma_f16(acc[8], a, oo);
                }
                BARA(3 + buf, 256);
            }
            // epilogue: unnormalized O + l partials
            const int r0 = i0 + wid * 16 + gid;
            float* ob = g_opart[half_] + ((size_t)b * NN) * HD;
            #pragma unroll
            for (int nc = 0; nc < 8; nc++) {
                int col = h * 64 + nc * 8 + 2 * tg;
                float2 v0 = {acc[nc][0], acc[nc][1]};
                float2 v1 = {acc[nc][2], acc[nc][3]};
                *(float2*)(ob + (size_t)r0 * HD + col) = v0;
                *(float2*)(ob + (size_t)(r0 + 8) * HD + col) = v1;
            }
            if (tg == 0) {
                g_lpart[half_][(size_t)bh * NN + r0] = acc[8][0];
                g_lpart[half_][(size_t)bh * NN + r0 + 8] = acc[8][2];
            }
        }
    }
}

// ---------------- K3: combine halves + normalize (8 floats/thread) ----------------
__global__ __launch_bounds__(256) void k3_combine(float* __restrict__ out) {
    int idx = blockIdx.x * 256 + threadIdx.x;
    size_t flat = (size_t)idx * 8;
    int b   = (int)(flat >> 19);           // / (NN*HD)
    int rem = (int)(flat & 524287);
    int i = rem >> 8;                      // / HD
    int h = (rem >> 6) & 3;
    size_t li = (size_t)(b * H + h) * NN + i;
    float l = g_lpart[0][li] + g_lpart[1][li];
    float inv = (l > 0.f) ? (1.f / l) : 0.f;
    float4 a0 = *(const float4*)(g_opart[0] + flat);
    float4 a1 = *(const float4*)(g_opart[0] + flat + 4);
    float4 b0 = *(const float4*)(g_opart[1] + flat);
    float4 b1 = *(const float4*)(g_opart[1] + flat + 4);
    float4 w0 = {(a0.x + b0.x) * inv, (a0.y + b0.y) * inv,
                 (a0.z + b0.z) * inv, (a0.w + b0.w) * inv};
    float4 w1 = {(a1.x + b1.x) * inv, (a1.y + b1.y) * inv,
                 (a1.z + b1.z) * inv, (a1.w + b1.w) * inv};
    *(float4*)(out + flat) = w0;
    *(float4*)(out + flat + 4) = w1;
}

extern "C" void kernel_launch(void* const* d_in, const int* in_sizes, int n_in,
                              void* d_out, int out_size) {
    const float* xs   = (const float*)d_in[0];
    const float* adjs = (const float*)d_in[1];
    const float* W1   = (const float*)d_in[2];
    const float* a_l  = (const float*)d_in[3];
    const float* a_r  = (const float*)d_in[4];
    float* out = (float*)d_out;

    cudaFuncSetAttribute(k2_attn, cudaFuncAttributeMaxDynamicSharedMemorySize, SMEM_K2);

    k1_gemm<<<dim3(32, 4, 4), 256>>>(xs, W1, a_l, a_r);
    k2_attn<<<dim3(32, 2, 4), 256, SMEM_K2>>>(adjs);
    k3_combine<<<(BS * NN * HD / 8) / 256, 256>>>(out);
}